// round 12
// baseline (speedup 1.0000x reference)
#include <cuda_runtime.h>
#include <stdint.h>

#define IN_CH   128
#define OUT_CH  32
#define MAX_N   100000
#define MAX_E   1600000
#define SCAN_B  256
#define SCAN_E  1024   // elements per scan block (256 thr x 4)

// Scratch (allocation-free rule: __device__ globals).
__device__ __align__(16) int d_deg_i   [MAX_N];
__device__ __align__(16) int d_rowstart[MAX_N];
__device__ __align__(16) int d_cursor  [MAX_N];
__device__ int   d_csr_src[MAX_E];
__device__ int   d_blocksum[256];
__device__ int   d_blockoff[256];
__device__ __align__(16) float d_dinv[MAX_N];
__device__ __align__(16) float d_g   [MAX_N * OUT_CH];
__device__ __align__(16) float d_z   [MAX_N * OUT_CH];
__device__ __align__(16) int2  d_edge[MAX_E];    // packed (src, dst)
__device__ int d_is64;

// ------------------------------------------------- K_detect: int64 vs int32?
__global__ void k_detect(const int* __restrict__ ei_w) {
    if (threadIdx.x == 0) {
        int acc = 0;
        for (int t = 0; t < 64; t++) acc |= ei_w[2 * t + 1];
        d_is64 = (acc == 0) ? 1 : 0;
    }
}

// ------------------------------------------------- K0: zero deg
__global__ void k_zero(int n) {
    int i = blockIdx.x * blockDim.x + threadIdx.x;
    if (i < n) d_deg_i[i] = 0;
}

// ------------------------------------------------- K1: convert + in-degree (fused)
__global__ void k_convert_degree(const int* __restrict__ ei_w, int E) {
    int e = blockIdx.x * blockDim.x + threadIdx.x;
    if (e >= E) return;
    int s, d;
    if (d_is64) {
        s = ei_w[2 * e];
        d = ei_w[2 * E + 2 * e];
    } else {
        s = ei_w[e];
        d = ei_w[E + e];
    }
    d_edge[e] = make_int2(s, d);
    atomicAdd(&d_deg_i[d], 1);
}

// ------------------------------------------------- scan phase 1: block sums
__global__ void k_scan1(int n) {
    __shared__ int wsum[8];
    int b = blockIdx.x, t = threadIdx.x;
    int base = b * SCAN_E + t * 4;
    int s = 0;
    if (base + 3 < n) {
        int4 v = *(const int4*)&d_deg_i[base];
        s = v.x + v.y + v.z + v.w;
    } else {
        for (int k = 0; k < 4; k++) if (base + k < n) s += d_deg_i[base + k];
    }
#pragma unroll
    for (int o = 16; o; o >>= 1) s += __shfl_down_sync(0xffffffffu, s, o);
    if ((t & 31) == 0) wsum[t >> 5] = s;
    __syncthreads();
    if (t == 0) {
        int tot = 0;
#pragma unroll
        for (int w = 0; w < 8; w++) tot += wsum[w];
        d_blocksum[b] = tot;
    }
}

// ------------------------------------------------- scan phase 2: scan block sums (1 block)
__global__ void k_scan2(int nb) {
    __shared__ int sh[256];
    int t = threadIdx.x;
    sh[t] = (t < nb) ? d_blocksum[t] : 0;
    __syncthreads();
    for (int o = 1; o < 256; o <<= 1) {
        int v = (t >= o) ? sh[t - o] : 0;
        __syncthreads();
        sh[t] += v;
        __syncthreads();
    }
    d_blockoff[t] = sh[t] - ((t < nb) ? d_blocksum[t] : 0);   // exclusive
}

// ------------------------------------------------- scan phase 3: final offsets
__global__ void k_scan3(int n) {
    __shared__ int woff[8];
    int b = blockIdx.x, t = threadIdx.x;
    int lane = t & 31, w = t >> 5;
    int base = b * SCAN_E + t * 4;
    int v[4];
#pragma unroll
    for (int k = 0; k < 4; k++) v[k] = (base + k < n) ? d_deg_i[base + k] : 0;
    int s = v[0] + v[1] + v[2] + v[3];
    int incl = s;
#pragma unroll
    for (int o = 1; o < 32; o <<= 1) {
        int u = __shfl_up_sync(0xffffffffu, incl, o);
        if (lane >= o) incl += u;
    }
    int excl = incl - s;
    if (lane == 31) woff[w] = incl;
    __syncthreads();
    if (t == 0) {
        int run = 0;
#pragma unroll
        for (int i = 0; i < 8; i++) { int tmp = woff[i]; woff[i] = run; run += tmp; }
    }
    __syncthreads();
    int off = d_blockoff[b] + woff[w] + excl;
#pragma unroll
    for (int k = 0; k < 4; k++) {
        if (base + k < n) {
            d_rowstart[base + k] = off;
            d_cursor[base + k]   = off;
            off += v[k];
        }
    }
}

// ------------------------------------------------- K_csr: fill per-dst source lists
__global__ void k_csr(int E) {
    int e = blockIdx.x * blockDim.x + threadIdx.x;
    if (e >= E) return;
    int2 sd = d_edge[e];
    int slot = atomicAdd(&d_cursor[sd.y], 1);
    d_csr_src[slot] = sd.x;
}

// ------------------------------------------------- K2: GEMM + dinv scale
// 2 rows/thread x 512-thread blocks (same 128 rows/block). Fewer registers
// (~45 vs 66) -> 2 blocks/SM = 32 warps = full occupancy to hide the
// 577-cyc DRAM latency on the x stream. Inner loop structure identical to
// the validated R6 form (unroll 2; ptxas schedules loads).
__global__ void __launch_bounds__(512) k_gemm(const float* __restrict__ x,
                                              const float* __restrict__ W, int n) {
    int tid = threadIdx.x;
    int rl  = tid >> 3;       // 0..63
    int cg  = tid & 7;        // 0..7
    int rbase = blockIdx.x * 128;

    int rows[2];
    const float4* xr[2];
#pragma unroll
    for (int m = 0; m < 2; m++) {
        rows[m] = rbase + rl + 64 * m;
        int rc = rows[m] < n ? rows[m] : (n - 1);   // clamp: safe load, guarded store
        xr[m] = (const float4*)(x + (size_t)rc * IN_CH);
    }
    const float* Wc = W + cg * 4;

    float a[2][4];
#pragma unroll
    for (int m = 0; m < 2; m++)
#pragma unroll
        for (int c = 0; c < 4; c++) a[m][c] = 0.0f;

#pragma unroll 2
    for (int kc = 0; kc < IN_CH / 4; kc++) {
        float4 xv[2];
#pragma unroll
        for (int m = 0; m < 2; m++) xv[m] = xr[m][kc];
        float4 w0 = *(const float4*)(Wc + (kc * 4 + 0) * OUT_CH);
        float4 w1 = *(const float4*)(Wc + (kc * 4 + 1) * OUT_CH);
        float4 w2 = *(const float4*)(Wc + (kc * 4 + 2) * OUT_CH);
        float4 w3 = *(const float4*)(Wc + (kc * 4 + 3) * OUT_CH);
#pragma unroll
        for (int m = 0; m < 2; m++) {
            a[m][0] += xv[m].x * w0.x; a[m][1] += xv[m].x * w0.y;
            a[m][2] += xv[m].x * w0.z; a[m][3] += xv[m].x * w0.w;
            a[m][0] += xv[m].y * w1.x; a[m][1] += xv[m].y * w1.y;
            a[m][2] += xv[m].y * w1.z; a[m][3] += xv[m].y * w1.w;
            a[m][0] += xv[m].z * w2.x; a[m][1] += xv[m].z * w2.y;
            a[m][2] += xv[m].z * w2.z; a[m][3] += xv[m].z * w2.w;
            a[m][0] += xv[m].w * w3.x; a[m][1] += xv[m].w * w3.y;
            a[m][2] += xv[m].w * w3.z; a[m][3] += xv[m].w * w3.w;
        }
    }

#pragma unroll
    for (int m = 0; m < 2; m++) {
        int row = rows[m];
        if (row < n) {
            float dinv = rsqrtf((float)d_deg_i[row] + 1.0f);   // +1 = self loop
            if (cg == 0) d_dinv[row] = dinv;
            float4 o = make_float4(a[m][0] * dinv, a[m][1] * dinv,
                                   a[m][2] * dinv, a[m][3] * dinv);
            *(float4*)&d_g[row * OUT_CH + cg * 4] = o;
        }
    }
}

// ------------------------------------------------- K3: gather + activate (fused, no atomics)
__global__ void k_gather_act(const float* __restrict__ b, int n) {
    int wid  = (blockIdx.x * blockDim.x + threadIdx.x) >> 5;
    int lane = threadIdx.x & 31;
    int grp  = lane >> 3;
    int sub  = lane & 7;
    int node = wid * 4 + grp;
    if (node >= n) return;

    int rs  = d_rowstart[node];
    int re  = rs + d_deg_i[node];
    float4 acc = *(const float4*)&d_g[node * OUT_CH + sub * 4];   // self loop

    int j = rs;
    for (; j + 1 < re; j += 2) {
        int s0 = d_csr_src[j];
        int s1 = d_csr_src[j + 1];
        float4 v0 = *(const float4*)&d_g[s0 * OUT_CH + sub * 4];
        float4 v1 = *(const float4*)&d_g[s1 * OUT_CH + sub * 4];
        acc.x += v0.x + v1.x; acc.y += v0.y + v1.y;
        acc.z += v0.z + v1.z; acc.w += v0.w + v1.w;
    }
    if (j < re) {
        int s0 = d_csr_src[j];
        float4 v0 = *(const float4*)&d_g[s0 * OUT_CH + sub * 4];
        acc.x += v0.x; acc.y += v0.y; acc.z += v0.z; acc.w += v0.w;
    }

    float dinv = d_dinv[node];
    float4 bv = *(const float4*)&b[sub * 4];
    float4 z;
    z.x = fmaxf(dinv * acc.x + bv.x, 0.0f);
    z.y = fmaxf(dinv * acc.y + bv.y, 0.0f);
    z.z = fmaxf(dinv * acc.z + bv.z, 0.0f);
    z.w = fmaxf(dinv * acc.w + bv.w, 0.0f);
    *(float4*)&d_z[node * OUT_CH + sub * 4] = z;
}

// ------------------------------------------------- K5: decoder
__global__ void k_decode(float* __restrict__ out, int E) {
    int wid  = (blockIdx.x * blockDim.x + threadIdx.x) >> 5;
    int lane = threadIdx.x & 31;
    int grp  = lane >> 3;
    int sub  = lane & 7;
    int e = wid * 4 + grp;
    if (e >= E) return;
    int2 sd = d_edge[e];
    float4 a = *(const float4*)&d_z[sd.x * OUT_CH + sub * 4];
    float4 c = *(const float4*)&d_z[sd.y * OUT_CH + sub * 4];
    float p = a.x * c.x + a.y * c.y + a.z * c.z + a.w * c.w;
    p += __shfl_xor_sync(0xffffffffu, p, 4);
    p += __shfl_xor_sync(0xffffffffu, p, 2);
    p += __shfl_xor_sync(0xffffffffu, p, 1);
    if (sub == 0) out[e] = 1.0f / (1.0f + __expf(-p));
}

// ------------------------------------------------- launch
extern "C" void kernel_launch(void* const* d_in, const int* in_sizes, int n_in,
                              void* d_out, int out_size) {
    const float* x    = (const float*)d_in[0];
    const int*   ei_w = (const int*)d_in[1];   // edge_index as 32-bit words
    const float* W    = (const float*)d_in[2];
    const float* b    = (const float*)d_in[3];
    float* out = (float*)d_out;

    int n = in_sizes[0] / IN_CH;      // 100000
    int E = in_sizes[1] / 2;          // 1600000
    int nb = (n + SCAN_E - 1) / SCAN_E;   // 98 scan blocks

    k_detect        <<<1, 32>>>(ei_w);
    k_zero          <<<(n + 255) / 256, 256>>>(n);
    k_convert_degree<<<(E + 255) / 256, 256>>>(ei_w, E);
    k_scan1         <<<nb, SCAN_B>>>(n);
    k_scan2         <<<1, 256>>>(nb);
    k_scan3         <<<nb, SCAN_B>>>(n);
    k_csr           <<<(E + 255) / 256, 256>>>(E);
    k_gemm          <<<(n + 127) / 128, 512>>>(x, W, n);
    {   // 8 threads per node
        long long threads = (long long)n * 8;
        k_gather_act<<<(int)((threads + 255) / 256), 256>>>(b, n);
    }
    {   // 8 threads per edge
        long long threads = (long long)E * 8;
        k_decode<<<(int)((threads + 255) / 256), 256>>>(out, E);
    }
}

// round 13
// speedup vs baseline: 1.0533x; 1.0533x over previous
#include <cuda_runtime.h>
#include <cuda_fp16.h>
#include <stdint.h>

#define IN_CH   128
#define OUT_CH  32
#define MAX_N   100000
#define MAX_E   1600000
#define SCAN_B  256
#define SCAN_E  1024   // elements per scan block (256 thr x 4)

// Scratch (allocation-free rule: __device__ globals).
__device__ __align__(16) int d_deg_i   [MAX_N];
__device__ __align__(16) int d_rowstart[MAX_N];
__device__ __align__(16) int d_cursor  [MAX_N];
__device__ int   d_csr_src[MAX_E];
__device__ int   d_blocksum[256];
__device__ int   d_blockoff[256];
__device__ __align__(16) float  d_dinv[MAX_N];
__device__ __align__(16) float  d_g   [MAX_N * OUT_CH];
__device__ __align__(16) __half d_z_h [MAX_N * OUT_CH];   // fp16 embeddings
__device__ __align__(16) int2   d_edge[MAX_E];            // packed (src, dst)
__device__ int d_is64;

// ------------------------------------------------- K_detect: int64 vs int32?
__global__ void k_detect(const int* __restrict__ ei_w) {
    if (threadIdx.x == 0) {
        int acc = 0;
        for (int t = 0; t < 64; t++) acc |= ei_w[2 * t + 1];
        d_is64 = (acc == 0) ? 1 : 0;
    }
}

// ------------------------------------------------- K0: zero deg
__global__ void k_zero(int n) {
    int i = blockIdx.x * blockDim.x + threadIdx.x;
    if (i < n) d_deg_i[i] = 0;
}

// ------------------------------------------------- K1: convert + in-degree (fused)
__global__ void k_convert_degree(const int* __restrict__ ei_w, int E) {
    int e = blockIdx.x * blockDim.x + threadIdx.x;
    if (e >= E) return;
    int s, d;
    if (d_is64) {
        s = ei_w[2 * e];
        d = ei_w[2 * E + 2 * e];
    } else {
        s = ei_w[e];
        d = ei_w[E + e];
    }
    d_edge[e] = make_int2(s, d);
    atomicAdd(&d_deg_i[d], 1);
}

// ------------------------------------------------- scan phase 1: block sums
__global__ void k_scan1(int n) {
    __shared__ int wsum[8];
    int b = blockIdx.x, t = threadIdx.x;
    int base = b * SCAN_E + t * 4;
    int s = 0;
    if (base + 3 < n) {
        int4 v = *(const int4*)&d_deg_i[base];
        s = v.x + v.y + v.z + v.w;
    } else {
        for (int k = 0; k < 4; k++) if (base + k < n) s += d_deg_i[base + k];
    }
#pragma unroll
    for (int o = 16; o; o >>= 1) s += __shfl_down_sync(0xffffffffu, s, o);
    if ((t & 31) == 0) wsum[t >> 5] = s;
    __syncthreads();
    if (t == 0) {
        int tot = 0;
#pragma unroll
        for (int w = 0; w < 8; w++) tot += wsum[w];
        d_blocksum[b] = tot;
    }
}

// ------------------------------------------------- scan phase 2: scan block sums (1 block)
__global__ void k_scan2(int nb) {
    __shared__ int sh[256];
    int t = threadIdx.x;
    sh[t] = (t < nb) ? d_blocksum[t] : 0;
    __syncthreads();
    for (int o = 1; o < 256; o <<= 1) {
        int v = (t >= o) ? sh[t - o] : 0;
        __syncthreads();
        sh[t] += v;
        __syncthreads();
    }
    d_blockoff[t] = sh[t] - ((t < nb) ? d_blocksum[t] : 0);   // exclusive
}

// ------------------------------------------------- scan phase 3: final offsets
__global__ void k_scan3(int n) {
    __shared__ int woff[8];
    int b = blockIdx.x, t = threadIdx.x;
    int lane = t & 31, w = t >> 5;
    int base = b * SCAN_E + t * 4;
    int v[4];
#pragma unroll
    for (int k = 0; k < 4; k++) v[k] = (base + k < n) ? d_deg_i[base + k] : 0;
    int s = v[0] + v[1] + v[2] + v[3];
    int incl = s;
#pragma unroll
    for (int o = 1; o < 32; o <<= 1) {
        int u = __shfl_up_sync(0xffffffffu, incl, o);
        if (lane >= o) incl += u;
    }
    int excl = incl - s;
    if (lane == 31) woff[w] = incl;
    __syncthreads();
    if (t == 0) {
        int run = 0;
#pragma unroll
        for (int i = 0; i < 8; i++) { int tmp = woff[i]; woff[i] = run; run += tmp; }
    }
    __syncthreads();
    int off = d_blockoff[b] + woff[w] + excl;
#pragma unroll
    for (int k = 0; k < 4; k++) {
        if (base + k < n) {
            d_rowstart[base + k] = off;
            d_cursor[base + k]   = off;
            off += v[k];
        }
    }
}

// ------------------------------------------------- K_csr: fill per-dst source lists
__global__ void k_csr(int E) {
    int e = blockIdx.x * blockDim.x + threadIdx.x;
    if (e >= E) return;
    int2 sd = d_edge[e];
    int slot = atomicAdd(&d_cursor[sd.y], 1);
    d_csr_src[slot] = sd.x;
}

// ------------------------------------------------- K2: GEMM + dinv scale (R11 form, known 46.6us)
__global__ void __launch_bounds__(256) k_gemm(const float* __restrict__ x,
                                              const float* __restrict__ W, int n) {
    int tid = threadIdx.x;
    int rl  = tid >> 3;       // 0..31
    int cg  = tid & 7;        // 0..7
    int rbase = blockIdx.x * 128;

    int rows[4];
    const float4* xr[4];
#pragma unroll
    for (int m = 0; m < 4; m++) {
        rows[m] = rbase + rl + 32 * m;
        int rc = rows[m] < n ? rows[m] : (n - 1);   // clamp: safe load, guarded store
        xr[m] = (const float4*)(x + (size_t)rc * IN_CH);
    }
    const float* Wc = W + cg * 4;

    float a[4][4];
#pragma unroll
    for (int m = 0; m < 4; m++)
#pragma unroll
        for (int c = 0; c < 4; c++) a[m][c] = 0.0f;

#pragma unroll 2
    for (int kc = 0; kc < IN_CH / 4; kc++) {
        float4 xv[4];
#pragma unroll
        for (int m = 0; m < 4; m++) xv[m] = xr[m][kc];
        float4 w0 = *(const float4*)(Wc + (kc * 4 + 0) * OUT_CH);
        float4 w1 = *(const float4*)(Wc + (kc * 4 + 1) * OUT_CH);
        float4 w2 = *(const float4*)(Wc + (kc * 4 + 2) * OUT_CH);
        float4 w3 = *(const float4*)(Wc + (kc * 4 + 3) * OUT_CH);
#pragma unroll
        for (int m = 0; m < 4; m++) {
            a[m][0] += xv[m].x * w0.x; a[m][1] += xv[m].x * w0.y;
            a[m][2] += xv[m].x * w0.z; a[m][3] += xv[m].x * w0.w;
            a[m][0] += xv[m].y * w1.x; a[m][1] += xv[m].y * w1.y;
            a[m][2] += xv[m].y * w1.z; a[m][3] += xv[m].y * w1.w;
            a[m][0] += xv[m].z * w2.x; a[m][1] += xv[m].z * w2.y;
            a[m][2] += xv[m].z * w2.z; a[m][3] += xv[m].z * w2.w;
            a[m][0] += xv[m].w * w3.x; a[m][1] += xv[m].w * w3.y;
            a[m][2] += xv[m].w * w3.z; a[m][3] += xv[m].w * w3.w;
        }
    }

#pragma unroll
    for (int m = 0; m < 4; m++) {
        int row = rows[m];
        if (row < n) {
            float dinv = rsqrtf((float)d_deg_i[row] + 1.0f);   // +1 = self loop
            if (cg == 0) d_dinv[row] = dinv;
            float4 o = make_float4(a[m][0] * dinv, a[m][1] * dinv,
                                   a[m][2] * dinv, a[m][3] * dinv);
            *(float4*)&d_g[row * OUT_CH + cg * 4] = o;
        }
    }
}

// ------------------------------------------------- K3: gather + activate, fp16 z out
__global__ void k_gather_act(const float* __restrict__ b, int n) {
    int wid  = (blockIdx.x * blockDim.x + threadIdx.x) >> 5;
    int lane = threadIdx.x & 31;
    int grp  = lane >> 3;
    int sub  = lane & 7;
    int node = wid * 4 + grp;
    if (node >= n) return;

    int rs  = d_rowstart[node];
    int re  = rs + d_deg_i[node];
    float4 acc = *(const float4*)&d_g[node * OUT_CH + sub * 4];   // self loop

    int j = rs;
    for (; j + 1 < re; j += 2) {
        int s0 = d_csr_src[j];
        int s1 = d_csr_src[j + 1];
        float4 v0 = *(const float4*)&d_g[s0 * OUT_CH + sub * 4];
        float4 v1 = *(const float4*)&d_g[s1 * OUT_CH + sub * 4];
        acc.x += v0.x + v1.x; acc.y += v0.y + v1.y;
        acc.z += v0.z + v1.z; acc.w += v0.w + v1.w;
    }
    if (j < re) {
        int s0 = d_csr_src[j];
        float4 v0 = *(const float4*)&d_g[s0 * OUT_CH + sub * 4];
        acc.x += v0.x; acc.y += v0.y; acc.z += v0.z; acc.w += v0.w;
    }

    float dinv = d_dinv[node];
    float4 bv = *(const float4*)&b[sub * 4];
    float zx = fmaxf(dinv * acc.x + bv.x, 0.0f);
    float zy = fmaxf(dinv * acc.y + bv.y, 0.0f);
    float zz = fmaxf(dinv * acc.z + bv.z, 0.0f);
    float zw = fmaxf(dinv * acc.w + bv.w, 0.0f);
    __half2 h0 = __floats2half2_rn(zx, zy);
    __half2 h1 = __floats2half2_rn(zz, zw);
    uint2 pk;
    pk.x = *(unsigned*)&h0;
    pk.y = *(unsigned*)&h1;
    *(uint2*)&d_z_h[node * OUT_CH + sub * 4] = pk;   // 8B per lane, row = 64B
}

// ------------------------------------------------- K5: decoder (fp16 z gathers, fp32 dot)
__global__ void k_decode(float* __restrict__ out, int E) {
    int wid  = (blockIdx.x * blockDim.x + threadIdx.x) >> 5;
    int lane = threadIdx.x & 31;
    int grp  = lane >> 3;
    int sub  = lane & 7;
    int e = wid * 4 + grp;
    if (e >= E) return;
    int2 sd = d_edge[e];
    uint2 pa = *(const uint2*)&d_z_h[sd.x * OUT_CH + sub * 4];
    uint2 pc = *(const uint2*)&d_z_h[sd.y * OUT_CH + sub * 4];
    float2 a0 = __half22float2(*(__half2*)&pa.x);
    float2 a1 = __half22float2(*(__half2*)&pa.y);
    float2 c0 = __half22float2(*(__half2*)&pc.x);
    float2 c1 = __half22float2(*(__half2*)&pc.y);
    float p = a0.x * c0.x + a0.y * c0.y + a1.x * c1.x + a1.y * c1.y;
    p += __shfl_xor_sync(0xffffffffu, p, 4);
    p += __shfl_xor_sync(0xffffffffu, p, 2);
    p += __shfl_xor_sync(0xffffffffu, p, 1);
    if (sub == 0) out[e] = 1.0f / (1.0f + __expf(-p));
}

// ------------------------------------------------- launch
extern "C" void kernel_launch(void* const* d_in, const int* in_sizes, int n_in,
                              void* d_out, int out_size) {
    const float* x    = (const float*)d_in[0];
    const int*   ei_w = (const int*)d_in[1];   // edge_index as 32-bit words
    const float* W    = (const float*)d_in[2];
    const float* b    = (const float*)d_in[3];
    float* out = (float*)d_out;

    int n = in_sizes[0] / IN_CH;      // 100000
    int E = in_sizes[1] / 2;          // 1600000
    int nb = (n + SCAN_E - 1) / SCAN_E;   // 98 scan blocks

    k_detect        <<<1, 32>>>(ei_w);
    k_zero          <<<(n + 255) / 256, 256>>>(n);
    k_convert_degree<<<(E + 255) / 256, 256>>>(ei_w, E);
    k_scan1         <<<nb, SCAN_B>>>(n);
    k_scan2         <<<1, 256>>>(nb);
    k_scan3         <<<nb, SCAN_B>>>(n);
    k_csr           <<<(E + 255) / 256, 256>>>(E);
    k_gemm          <<<(n + 127) / 128, 256>>>(x, W, n);
    {   // 8 threads per node
        long long threads = (long long)n * 8;
        k_gather_act<<<(int)((threads + 255) / 256), 256>>>(b, n);
    }
    {   // 8 threads per edge
        long long threads = (long long)E * 8;
        k_decode<<<(int)((threads + 255) / 256), 256>>>(out, E);
    }
}

// round 16
// speedup vs baseline: 1.2543x; 1.1908x over previous
#include <cuda_runtime.h>
#include <cuda_fp16.h>
#include <stdint.h>

#define IN_CH   128
#define OUT_CH  32
#define MAX_N   100000
#define MAX_E   1600000
#define SCAN_B  256
#define SCAN_E  1024   // elements per scan block (256 thr x 4)

// Scratch (allocation-free rule: __device__ globals).
__device__ __align__(16) int d_deg_i   [MAX_N];
__device__ __align__(16) int d_rowstart[MAX_N];
__device__ __align__(16) int d_cursor  [MAX_N];
__device__ int   d_csr_src[MAX_E];
__device__ int   d_blocksum[256];
__device__ int   d_blockoff[256];
__device__ __align__(16) float  d_dinv[MAX_N];
__device__ __align__(16) __half d_g_h [MAX_N * OUT_CH];   // fp16 pre-scaled features
__device__ __align__(16) __half d_z_h [MAX_N * OUT_CH];   // fp16 embeddings
__device__ __align__(16) int2   d_edge[MAX_E];            // packed (src, dst)
__device__ int d_is64;

// ------------------------------------------------- K_detect: int64 vs int32?
__global__ void k_detect(const int* __restrict__ ei_w) {
    if (threadIdx.x == 0) {
        int acc = 0;
        for (int t = 0; t < 64; t++) acc |= ei_w[2 * t + 1];
        d_is64 = (acc == 0) ? 1 : 0;
    }
}

// ------------------------------------------------- K0: zero deg
__global__ void k_zero(int n) {
    int i = blockIdx.x * blockDim.x + threadIdx.x;
    if (i < n) d_deg_i[i] = 0;
}

// ------------------------------------------------- K1: convert + in-degree (fused)
__global__ void k_convert_degree(const int* __restrict__ ei_w, int E) {
    int e = blockIdx.x * blockDim.x + threadIdx.x;
    if (e >= E) return;
    int s, d;
    if (d_is64) {
        s = ei_w[2 * e];
        d = ei_w[2 * E + 2 * e];
    } else {
        s = ei_w[e];
        d = ei_w[E + e];
    }
    d_edge[e] = make_int2(s, d);
    atomicAdd(&d_deg_i[d], 1);
}

// ------------------------------------------------- scan phase 1: block sums
__global__ void k_scan1(int n) {
    __shared__ int wsum[8];
    int b = blockIdx.x, t = threadIdx.x;
    int base = b * SCAN_E + t * 4;
    int s = 0;
    if (base + 3 < n) {
        int4 v = *(const int4*)&d_deg_i[base];
        s = v.x + v.y + v.z + v.w;
    } else {
        for (int k = 0; k < 4; k++) if (base + k < n) s += d_deg_i[base + k];
    }
#pragma unroll
    for (int o = 16; o; o >>= 1) s += __shfl_down_sync(0xffffffffu, s, o);
    if ((t & 31) == 0) wsum[t >> 5] = s;
    __syncthreads();
    if (t == 0) {
        int tot = 0;
#pragma unroll
        for (int w = 0; w < 8; w++) tot += wsum[w];
        d_blocksum[b] = tot;
    }
}

// ------------------------------------------------- scan phase 2: scan block sums (1 block)
__global__ void k_scan2(int nb) {
    __shared__ int sh[256];
    int t = threadIdx.x;
    sh[t] = (t < nb) ? d_blocksum[t] : 0;
    __syncthreads();
    for (int o = 1; o < 256; o <<= 1) {
        int v = (t >= o) ? sh[t - o] : 0;
        __syncthreads();
        sh[t] += v;
        __syncthreads();
    }
    d_blockoff[t] = sh[t] - ((t < nb) ? d_blocksum[t] : 0);   // exclusive
}

// ------------------------------------------------- scan phase 3: final offsets
__global__ void k_scan3(int n) {
    __shared__ int woff[8];
    int b = blockIdx.x, t = threadIdx.x;
    int lane = t & 31, w = t >> 5;
    int base = b * SCAN_E + t * 4;
    int v[4];
#pragma unroll
    for (int k = 0; k < 4; k++) v[k] = (base + k < n) ? d_deg_i[base + k] : 0;
    int s = v[0] + v[1] + v[2] + v[3];
    int incl = s;
#pragma unroll
    for (int o = 1; o < 32; o <<= 1) {
        int u = __shfl_up_sync(0xffffffffu, incl, o);
        if (lane >= o) incl += u;
    }
    int excl = incl - s;
    if (lane == 31) woff[w] = incl;
    __syncthreads();
    if (t == 0) {
        int run = 0;
#pragma unroll
        for (int i = 0; i < 8; i++) { int tmp = woff[i]; woff[i] = run; run += tmp; }
    }
    __syncthreads();
    int off = d_blockoff[b] + woff[w] + excl;
#pragma unroll
    for (int k = 0; k < 4; k++) {
        if (base + k < n) {
            d_rowstart[base + k] = off;
            d_cursor[base + k]   = off;
            off += v[k];
        }
    }
}

// ------------------------------------------------- K_csr: fill per-dst source lists
__global__ void k_csr(int E) {
    int e = blockIdx.x * blockDim.x + threadIdx.x;
    if (e >= E) return;
    int2 sd = d_edge[e];
    int slot = atomicAdd(&d_cursor[sd.y], 1);
    d_csr_src[slot] = sd.x;
}

// ------------------------------------------------- K2: GEMM + dinv scale (R11 loop), fp16 g out
__global__ void __launch_bounds__(256) k_gemm(const float* __restrict__ x,
                                              const float* __restrict__ W, int n) {
    int tid = threadIdx.x;
    int rl  = tid >> 3;       // 0..31
    int cg  = tid & 7;        // 0..7
    int rbase = blockIdx.x * 128;

    int rows[4];
    const float4* xr[4];
#pragma unroll
    for (int m = 0; m < 4; m++) {
        rows[m] = rbase + rl + 32 * m;
        int rc = rows[m] < n ? rows[m] : (n - 1);   // clamp: safe load, guarded store
        xr[m] = (const float4*)(x + (size_t)rc * IN_CH);
    }
    const float* Wc = W + cg * 4;

    float a[4][4];
#pragma unroll
    for (int m = 0; m < 4; m++)
#pragma unroll
        for (int c = 0; c < 4; c++) a[m][c] = 0.0f;

#pragma unroll 2
    for (int kc = 0; kc < IN_CH / 4; kc++) {
        float4 xv[4];
#pragma unroll
        for (int m = 0; m < 4; m++) xv[m] = xr[m][kc];
        float4 w0 = *(const float4*)(Wc + (kc * 4 + 0) * OUT_CH);
        float4 w1 = *(const float4*)(Wc + (kc * 4 + 1) * OUT_CH);
        float4 w2 = *(const float4*)(Wc + (kc * 4 + 2) * OUT_CH);
        float4 w3 = *(const float4*)(Wc + (kc * 4 + 3) * OUT_CH);
#pragma unroll
        for (int m = 0; m < 4; m++) {
            a[m][0] += xv[m].x * w0.x; a[m][1] += xv[m].x * w0.y;
            a[m][2] += xv[m].x * w0.z; a[m][3] += xv[m].x * w0.w;
            a[m][0] += xv[m].y * w1.x; a[m][1] += xv[m].y * w1.y;
            a[m][2] += xv[m].y * w1.z; a[m][3] += xv[m].y * w1.w;
            a[m][0] += xv[m].z * w2.x; a[m][1] += xv[m].z * w2.y;
            a[m][2] += xv[m].z * w2.z; a[m][3] += xv[m].z * w2.w;
            a[m][0] += xv[m].w * w3.x; a[m][1] += xv[m].w * w3.y;
            a[m][2] += xv[m].w * w3.z; a[m][3] += xv[m].w * w3.w;
        }
    }

#pragma unroll
    for (int m = 0; m < 4; m++) {
        int row = rows[m];
        if (row < n) {
            float dinv = rsqrtf((float)d_deg_i[row] + 1.0f);   // +1 = self loop
            if (cg == 0) d_dinv[row] = dinv;
            __half2 h0 = __floats2half2_rn(a[m][0] * dinv, a[m][1] * dinv);
            __half2 h1 = __floats2half2_rn(a[m][2] * dinv, a[m][3] * dinv);
            uint2 pk;
            pk.x = *(unsigned*)&h0;
            pk.y = *(unsigned*)&h1;
            *(uint2*)&d_g_h[row * OUT_CH + cg * 4] = pk;
        }
    }
}

// ------------------------------------------------- K3: gather + activate (fp16 g in, fp32 accum, fp16 z out)
__global__ void k_gather_act(const float* __restrict__ b, int n) {
    int wid  = (blockIdx.x * blockDim.x + threadIdx.x) >> 5;
    int lane = threadIdx.x & 31;
    int grp  = lane >> 3;
    int sub  = lane & 7;
    int node = wid * 4 + grp;
    if (node >= n) return;

    int rs  = d_rowstart[node];
    int re  = rs + d_deg_i[node];

    // self-loop term
    uint2 ps = *(const uint2*)&d_g_h[node * OUT_CH + sub * 4];
    float2 s0f = __half22float2(*(__half2*)&ps.x);
    float2 s1f = __half22float2(*(__half2*)&ps.y);
    float4 acc = make_float4(s0f.x, s0f.y, s1f.x, s1f.y);

    int j = rs;
    for (; j + 1 < re; j += 2) {
        int q0 = d_csr_src[j];
        int q1 = d_csr_src[j + 1];
        uint2 p0 = *(const uint2*)&d_g_h[q0 * OUT_CH + sub * 4];
        uint2 p1 = *(const uint2*)&d_g_h[q1 * OUT_CH + sub * 4];
        float2 a0 = __half22float2(*(__half2*)&p0.x);
        float2 a1 = __half22float2(*(__half2*)&p0.y);
        float2 b0 = __half22float2(*(__half2*)&p1.x);
        float2 b1 = __half22float2(*(__half2*)&p1.y);
        acc.x += a0.x + b0.x; acc.y += a0.y + b0.y;
        acc.z += a1.x + b1.x; acc.w += a1.y + b1.y;
    }
    if (j < re) {
        int q0 = d_csr_src[j];
        uint2 p0 = *(const uint2*)&d_g_h[q0 * OUT_CH + sub * 4];
        float2 a0 = __half22float2(*(__half2*)&p0.x);
        float2 a1 = __half22float2(*(__half2*)&p0.y);
        acc.x += a0.x; acc.y += a0.y; acc.z += a1.x; acc.w += a1.y;
    }

    float dinv = d_dinv[node];
    float4 bv = *(const float4*)&b[sub * 4];
    float zx = fmaxf(dinv * acc.x + bv.x, 0.0f);
    float zy = fmaxf(dinv * acc.y + bv.y, 0.0f);
    float zz = fmaxf(dinv * acc.z + bv.z, 0.0f);
    float zw = fmaxf(dinv * acc.w + bv.w, 0.0f);
    __half2 h0 = __floats2half2_rn(zx, zy);
    __half2 h1 = __floats2half2_rn(zz, zw);
    uint2 pk;
    pk.x = *(unsigned*)&h0;
    pk.y = *(unsigned*)&h1;
    *(uint2*)&d_z_h[node * OUT_CH + sub * 4] = pk;   // 8B per lane, row = 64B
}

// ------------------------------------------------- K5: decoder — 4 lanes/edge, LDG.128 of fp16 rows
__global__ void k_decode(float* __restrict__ out, int E) {
    int wid  = (blockIdx.x * blockDim.x + threadIdx.x) >> 5;
    int lane = threadIdx.x & 31;
    int grp  = lane >> 2;     // edge within warp (0..7)
    int sub  = lane & 3;      // 16B slot within 64B row
    int e = wid * 8 + grp;
    if (e >= E) return;
    int2 sd = d_edge[e];
    uint4 pa = *(const uint4*)&d_z_h[sd.x * OUT_CH + sub * 8];
    uint4 pc = *(const uint4*)&d_z_h[sd.y * OUT_CH + sub * 8];
    float2 a0 = __half22float2(*(__half2*)&pa.x);
    float2 a1 = __half22float2(*(__half2*)&pa.y);
    float2 a2 = __half22float2(*(__half2*)&pa.z);
    float2 a3 = __half22float2(*(__half2*)&pa.w);
    float2 c0 = __half22float2(*(__half2*)&pc.x);
    float2 c1 = __half22float2(*(__half2*)&pc.y);
    float2 c2 = __half22float2(*(__half2*)&pc.z);
    float2 c3 = __half22float2(*(__half2*)&pc.w);
    float p = a0.x * c0.x + a0.y * c0.y + a1.x * c1.x + a1.y * c1.y
            + a2.x * c2.x + a2.y * c2.y + a3.x * c3.x + a3.y * c3.y;
    p += __shfl_xor_sync(0xffffffffu, p, 2);
    p += __shfl_xor_sync(0xffffffffu, p, 1);
    if (sub == 0) out[e] = 1.0f / (1.0f + __expf(-p));
}

// ------------------------------------------------- launch
extern "C" void kernel_launch(void* const* d_in, const int* in_sizes, int n_in,
                              void* d_out, int out_size) {
    const float* x    = (const float*)d_in[0];
    const int*   ei_w = (const int*)d_in[1];   // edge_index as 32-bit words
    const float* W    = (const float*)d_in[2];
    const float* b    = (const float*)d_in[3];
    float* out = (float*)d_out;

    int n = in_sizes[0] / IN_CH;      // 100000
    int E = in_sizes[1] / 2;          // 1600000
    int nb = (n + SCAN_E - 1) / SCAN_E;   // 98 scan blocks

    k_detect        <<<1, 32>>>(ei_w);
    k_zero          <<<(n + 255) / 256, 256>>>(n);
    k_convert_degree<<<(E + 255) / 256, 256>>>(ei_w, E);
    k_scan1         <<<nb, SCAN_B>>>(n);
    k_scan2         <<<1, 256>>>(nb);
    k_scan3         <<<nb, SCAN_B>>>(n);
    k_csr           <<<(E + 255) / 256, 256>>>(E);
    k_gemm          <<<(n + 127) / 128, 256>>>(x, W, n);
    {   // 8 threads per node
        long long threads = (long long)n * 8;
        k_gather_act<<<(int)((threads + 255) / 256), 256>>>(b, n);
    }
    {   // 4 threads per edge
        long long threads = (long long)E * 4;
        k_decode<<<(int)((threads + 255) / 256), 256>>>(out, E);
    }
}